// round 12
// baseline (speedup 1.0000x reference)
#include <cuda_runtime.h>
#include <cuda_bf16.h>
#include <cstdint>

// Problem constants
#define BB   4
#define SS   2048
#define DD   512
#define HH   8
#define HD   64
#define NTOK (BB*SS)          // 8192
#define QKV_N (3*DD)          // 1536
#define SCALE 0.125f          // HD^-0.5

// ---------------- scratch (__device__ globals) ------------------------------
static __device__ uint32_t g_qb[BB*HH*SS*(HD/2)];      // 8 MB Q bf16 pairs [bh][s][dp]
static __device__ uint32_t g_kb[BB*HH*SS*(HD/2)];      // 8 MB K bf16 pairs [bh][s][dp]
static __device__ float    g_v [BB*HH*SS*HD];          // 16 MB fp32
static __device__ uint32_t g_vb[BB*HH*HD*(SS/2)];      // 8 MB V bf16 pairs [bh][d][kp]
static __device__ uint32_t g_eb[BB*HH*SS*(SS/2)];      // 256 MB E bf16 [b][j][q][kp]
static __device__ float    g_ao[NTOK*DD];              // 16 MB fp32
static __device__ float    g_l[BB*HH*SS];              // softmax denominators
static __device__ float    g_vs[BB*HH*HD];             // colsum of V per (b,h)

// ---------------- helpers ---------------------------------------------------
__device__ __forceinline__ uint32_t f2tf32(float f) {
    uint32_t u;
    asm("cvt.rna.tf32.f32 %0, %1;" : "=r"(u) : "f"(f));
    return u;
}

__device__ __forceinline__ void mma_tf32(float* c,
                                         uint32_t a0, uint32_t a1, uint32_t a2, uint32_t a3,
                                         uint32_t b0, uint32_t b1) {
    asm volatile(
        "mma.sync.aligned.m16n8k8.row.col.f32.tf32.tf32.f32 "
        "{%0,%1,%2,%3}, {%4,%5,%6,%7}, {%8,%9}, {%0,%1,%2,%3};\n"
        : "+f"(c[0]), "+f"(c[1]), "+f"(c[2]), "+f"(c[3])
        : "r"(a0), "r"(a1), "r"(a2), "r"(a3), "r"(b0), "r"(b1));
}

__device__ __forceinline__ void mma_bf16(float* c,
                                         uint32_t a0, uint32_t a1, uint32_t a2, uint32_t a3,
                                         uint32_t b0, uint32_t b1) {
    asm volatile(
        "mma.sync.aligned.m16n8k16.row.col.f32.bf16.bf16.f32 "
        "{%0,%1,%2,%3}, {%4,%5,%6,%7}, {%8,%9}, {%0,%1,%2,%3};\n"
        : "+f"(c[0]), "+f"(c[1]), "+f"(c[2]), "+f"(c[3])
        : "r"(a0), "r"(a1), "r"(a2), "r"(a3), "r"(b0), "r"(b1));
}

__device__ __forceinline__ uint32_t pack_bf16(float lo, float hi) {
    __nv_bfloat162 p = __floats2bfloat162_rn(lo, hi);
    return *reinterpret_cast<uint32_t*>(&p);
}

__device__ __forceinline__ float bf16lo(uint32_t u) { return __uint_as_float(u << 16); }
__device__ __forceinline__ float bf16hi(uint32_t u) { return __uint_as_float(u & 0xffff0000u); }

// Stage a 64x64 fp32 tile (row stride ld floats) into tf32 smem [64][68].
__device__ __forceinline__ void stage_tile(uint32_t (*S)[68], const float* __restrict__ src,
                                           size_t ld, int tid) {
    for (int f = tid; f < 1024; f += 256) {
        int r = f >> 4, c = (f & 15) << 2;
        float4 v = *(const float4*)&src[(size_t)r * ld + c];
        uint4 u;
        u.x = f2tf32(v.x); u.y = f2tf32(v.y); u.z = f2tf32(v.z); u.w = f2tf32(v.w);
        *(uint4*)&S[r][c] = u;
    }
}

#define STRD 36   // smem row stride (u32) for 32-pair bf16 tiles

// ============================================================================
// Kernel 1: QKV GEMM (tf32 mma, fp32 inputs). Q,K -> bf16 pairs; V -> fp32.
// (R7-proven version.)
// ============================================================================
__global__ __launch_bounds__(256) void k_qkv(const float* __restrict__ x,
                                             const float* __restrict__ w) {
    __shared__ uint32_t As[64][68];
    __shared__ uint32_t Bs[64][68];
    const int tid = threadIdx.x;
    const int lane = tid & 31, warp = tid >> 5;
    const int g = lane >> 2, t = lane & 3;
    const int q0 = (warp >> 1) * 16, n0c = (warp & 1) * 32;
    const int m0 = blockIdx.y * 64;
    const int n0 = blockIdx.x * 64;

    float c[4][4] = {};
    for (int k0 = 0; k0 < DD; k0 += 64) {
        stage_tile(As, &x[(size_t)m0 * DD + k0], DD, tid);
        stage_tile(Bs, &w[(size_t)n0 * DD + k0], DD, tid);
        __syncthreads();
        #pragma unroll
        for (int kk = 0; kk < 64; kk += 8) {
            uint32_t a0 = As[q0 + g][kk + t];
            uint32_t a1 = As[q0 + g + 8][kk + t];
            uint32_t a2 = As[q0 + g][kk + t + 4];
            uint32_t a3 = As[q0 + g + 8][kk + t + 4];
            #pragma unroll
            for (int j = 0; j < 4; j++) {
                uint32_t b0 = Bs[n0c + 8*j + g][kk + t];
                uint32_t b1 = Bs[n0c + 8*j + g][kk + t + 4];
                mma_tf32(c[j], a0, a1, a2, a3, b0, b1);
            }
        }
        __syncthreads();
    }
    const int which = n0 >> 9;
    const int h     = (n0 >> 6) & 7;
    const int b     = m0 / SS;
    const int sbase = m0 % SS;
    const size_t bh = (size_t)b*HH + h;
    if (which == 2) {
        #pragma unroll
        for (int j = 0; j < 4; j++) {
            int col = n0c + 8*j + 2*t;
            *(float2*)&g_v[(bh*SS + sbase + q0 + g    )*HD + col] = make_float2(c[j][0], c[j][1]);
            *(float2*)&g_v[(bh*SS + sbase + q0 + g + 8)*HD + col] = make_float2(c[j][2], c[j][3]);
        }
    } else {
        uint32_t* dst = (which == 0) ? g_qb : g_kb;
        const float mul = (which == 0) ? SCALE : 1.0f;
        #pragma unroll
        for (int j = 0; j < 4; j++) {
            int dp = (n0c + 8*j + 2*t) >> 1;
            dst[(bh*SS + sbase + q0 + g    )*(HD/2) + dp] = pack_bf16(c[j][0]*mul, c[j][1]*mul);
            dst[(bh*SS + sbase + q0 + g + 8)*(HD/2) + dp] = pack_bf16(c[j][2]*mul, c[j][3]*mul);
        }
    }
}

// ============================================================================
// Kernel 2a: zero softmax-denominator accumulator.
// ============================================================================
__global__ __launch_bounds__(256) void k_zero() {
    int i = blockIdx.x * 256 + threadIdx.x;
    if (i < BB*HH*SS) g_l[i] = 0.f;
}

// ============================================================================
// Kernel 2b: V column sums. grid = BB*HH.
// ============================================================================
__global__ __launch_bounds__(256) void k_vsum() {
    __shared__ float red[4][64];
    const int tid = threadIdx.x;
    const int bh = blockIdx.x;
    const int d = tid & 63, seg = tid >> 6;
    const float* vp = &g_v[(size_t)bh * SS * HD];
    float s = 0.f;
    for (int r = seg*512; r < (seg+1)*512; r++) s += vp[(size_t)r*HD + d];
    red[seg][d] = s;
    __syncthreads();
    if (tid < 64)
        g_vs[(size_t)bh*HD + tid] = red[0][tid] + red[1][tid] + red[2][tid] + red[3][tid];
}

// ============================================================================
// Kernel 2c: transpose+pack V -> g_vb[b][h][d][kp] bf16 k-pairs.
// ============================================================================
__global__ __launch_bounds__(256) void k_packv() {
    __shared__ float sT[64][65];
    const int tid = threadIdx.x;
    const int bh = blockIdx.x;
    const int kt = blockIdx.y * 64;
    const float* vp = &g_v[((size_t)bh*SS + kt)*HD];
    for (int i = tid; i < 1024; i += 256) {
        int r = i >> 4, c = (i & 15) << 2;
        float4 v = *(const float4*)&vp[(size_t)r*HD + c];
        sT[r][c] = v.x; sT[r][c+1] = v.y; sT[r][c+2] = v.z; sT[r][c+3] = v.w;
    }
    __syncthreads();
    for (int i = tid; i < 2048; i += 256) {
        int kp = i & 31, d = i >> 5;
        g_vb[((size_t)bh*HD + d)*(SS/2) + (kt >> 1) + kp] =
            pack_bf16(sT[2*kp][d], sT[2*kp+1][d]);
    }
}

// ============================================================================
// Kernel 3: scores + pre-mix (bf16 mma, 32x64 tile, occ 2, double-buffered).
// Stores E = exp(L + b_l) bf16 and accumulates denominators l_j[q].
// (R7-proven version.)
// ============================================================================
__global__ __launch_bounds__(256, 2) void k_scores(const float* __restrict__ wl,
                                                   const float* __restrict__ bl) {
    __shared__ uint32_t sQ[2][32*STRD];
    __shared__ uint32_t sK[2][64*STRD];
    __shared__ float s_wl[64];
    const int tid = threadIdx.x;
    const int lane = tid & 31, warp = tid >> 5;
    const int g = lane >> 2, t = lane & 3;
    const int q0 = (warp >> 2) * 16;
    const int n0 = (warp & 3) * 16;
    const int kt = blockIdx.x * 64;
    const int qt = blockIdx.y * 32;
    const int b  = blockIdx.z;

    if (tid < 64) s_wl[tid] = wl[tid];

    float blr[8];
    #pragma unroll
    for (int j = 0; j < 8; j++) blr[j] = __ldg(&bl[j]);

    const int qr = tid >> 3, qc = (tid & 7) * 4;
    const int kr = tid >> 2, kc = (tid & 3) * 8;

    float acc[8][8];
    #pragma unroll
    for (int j = 0; j < 8; j++)
        #pragma unroll
        for (int e = 0; e < 8; e++) acc[j][e] = 0.f;

    {
        const uint32_t* Qp = &g_qb[(((size_t)b*HH + 0)*SS + qt)*(HD/2)];
        const uint32_t* Kp = &g_kb[(((size_t)b*HH + 0)*SS + kt)*(HD/2)];
        *(uint4*)&sQ[0][qr*STRD + qc] = *(const uint4*)&Qp[qr*32 + qc];
        *(uint4*)&sK[0][kr*STRD + kc    ] = *(const uint4*)&Kp[kr*32 + kc];
        *(uint4*)&sK[0][kr*STRD + kc + 4] = *(const uint4*)&Kp[kr*32 + kc + 4];
    }

    for (int h = 0; h < 8; h++) {
        __syncthreads();
        if (h < 7) {
            const int nb = (h+1) & 1;
            const uint32_t* Qp = &g_qb[(((size_t)b*HH + h+1)*SS + qt)*(HD/2)];
            const uint32_t* Kp = &g_kb[(((size_t)b*HH + h+1)*SS + kt)*(HD/2)];
            *(uint4*)&sQ[nb][qr*STRD + qc] = *(const uint4*)&Qp[qr*32 + qc];
            *(uint4*)&sK[nb][kr*STRD + kc    ] = *(const uint4*)&Kp[kr*32 + kc];
            *(uint4*)&sK[nb][kr*STRD + kc + 4] = *(const uint4*)&Kp[kr*32 + kc + 4];
        }
        const int cb = h & 1;
        float s[2][4] = {};
        #pragma unroll
        for (int ck = 0; ck < 4; ck++) {
            uint32_t a0 = sQ[cb][(q0 + g    )*STRD + ck*8 + t];
            uint32_t a1 = sQ[cb][(q0 + g + 8)*STRD + ck*8 + t];
            uint32_t a2 = sQ[cb][(q0 + g    )*STRD + ck*8 + t + 4];
            uint32_t a3 = sQ[cb][(q0 + g + 8)*STRD + ck*8 + t + 4];
            #pragma unroll
            for (int jt = 0; jt < 2; jt++) {
                uint32_t b0 = sK[cb][(n0 + jt*8 + g)*STRD + ck*8 + t];
                uint32_t b1 = sK[cb][(n0 + jt*8 + g)*STRD + ck*8 + t + 4];
                mma_bf16(s[jt], a0, a1, a2, a3, b0, b1);
            }
        }
        #pragma unroll
        for (int j = 0; j < 8; j++) {
            float wv = s_wl[j*8 + h];
            #pragma unroll
            for (int jt = 0; jt < 2; jt++)
                #pragma unroll
                for (int e = 0; e < 4; e++)
                    acc[j][jt*4+e] += wv * s[jt][e];
        }
    }

    const int r0 = qt + q0 + g, r1 = r0 + 8;
    #pragma unroll
    for (int j = 0; j < 8; j++) {
        float blv = blr[j];
        size_t rb0 = (((size_t)b*HH + j)*SS + r0) * (SS/2);
        size_t rb1 = (((size_t)b*HH + j)*SS + r1) * (SS/2);
        float l0 = 0.f, l1 = 0.f;
        #pragma unroll
        for (int jt = 0; jt < 2; jt++) {
            int kp = (kt + n0 + jt*8 + 2*t) >> 1;
            float e0 = __expf(acc[j][jt*4+0] + blv);
            float e1 = __expf(acc[j][jt*4+1] + blv);
            float e2 = __expf(acc[j][jt*4+2] + blv);
            float e3 = __expf(acc[j][jt*4+3] + blv);
            g_eb[rb0 + kp] = pack_bf16(e0, e1);
            g_eb[rb1 + kp] = pack_bf16(e2, e3);
            l0 += e0 + e1;
            l1 += e2 + e3;
        }
        l0 += __shfl_xor_sync(0xffffffffu, l0, 1);
        l0 += __shfl_xor_sync(0xffffffffu, l0, 2);
        l1 += __shfl_xor_sync(0xffffffffu, l1, 1);
        l1 += __shfl_xor_sync(0xffffffffu, l1, 2);
        if (t == 0) {
            atomicAdd(&g_l[((size_t)b*HH + j)*SS + r0], l0);
            atomicAdd(&g_l[((size_t)b*HH + j)*SS + r1], l1);
        }
    }
}

// ============================================================================
// Kernel 4: fused mix + AV, ALL 8 heads per CTA (bf16 mma, double-buffered).
// CTA = (qt32, b), grid (64, 4). Each CTA reads each E element exactly ONCE
// (1x amplification), mixes into 8 W tiles, runs 8 AV GEMMs, 1 sync/iter.
// smem: sW[2][8][32][18] + sV[2][8][64][18] u32 = 110592 B -> occ 2.
// ============================================================================
#define WST 18
#define AVF_W_BUF (8*32*WST)                       // 4608 u32
#define AVF_V_BUF (8*64*WST)                       // 9216 u32
#define AVF_SMEM ((2*AVF_W_BUF + 2*AVF_V_BUF)*4)   // 110592 B

__global__ __launch_bounds__(256, 2) void k_avfull(const float* __restrict__ ww,
                                                   const float* __restrict__ bw) {
    extern __shared__ uint32_t dyn[];
    uint32_t* sWb = dyn;                    // [2][8][32][WST]
    uint32_t* sVb = dyn + 2*AVF_W_BUF;      // [2][8][64][WST]
    __shared__ float s_ww[64];

    const int tid = threadIdx.x;
    const int lane = tid & 31, warp = tid >> 5;
    const int g = lane >> 2, t = lane & 3;
    const int q0 = (warp >> 2) * 16;        // 0 or 16
    const int d0 = (warp & 3) * 16;         // 0,16,32,48
    const int qt = blockIdx.x * 32;
    const int b  = blockIdx.y;

    if (tid < 64) s_ww[tid] = ww[tid];

    // E staging: er = q-row (32 rows, 8 thr/row), kq = kp offset (2 per thread)
    const int er = tid >> 3, kq = (tid & 7) * 2;
    // V staging: vh = head (32 thr/head), vd = d row pair base
    const int vh = tid >> 5, vd = (tid & 31) * 2;

    float invl[8];
    #pragma unroll
    for (int j = 0; j < 8; j++)
        invl[j] = 1.0f / g_l[((size_t)b*HH + j)*SS + qt + er];

    const size_t ejstride = (size_t)SS*(SS/2);
    const uint32_t* Ebase = &g_eb[((size_t)b*HH*SS + qt + er) * (SS/2)];
    const uint32_t* Vb0 = &g_vb[(((size_t)b*HH + vh)*HD + vd) * (SS/2)];
    __syncthreads();   // s_ww visible

    // ---- staging: mix E->W (all 8 output heads) + copy V, for one kt32 tile
    #define STAGE_AVF(BUF, KP0)                                                \
    {                                                                          \
        /* V: 2 d-rows x 16 kp, uint4 gmem loads, uint2 smem stores */         \
        _Pragma("unroll")                                                      \
        for (int r = 0; r < 2; r++) {                                          \
            uint4 v0 = *(const uint4*)&Vb0[(size_t)r*(SS/2) + (KP0)];          \
            uint4 v1 = *(const uint4*)&Vb0[(size_t)r*(SS/2) + (KP0) + 4];      \
            uint4 v2 = *(const uint4*)&Vb0[(size_t)r*(SS/2) + (KP0) + 8];      \
            uint4 v3 = *(const uint4*)&Vb0[(size_t)r*(SS/2) + (KP0) + 12];     \
            uint32_t* vp = &sVb[(BUF)*AVF_V_BUF + vh*64*WST + (vd + r)*WST];   \
            *(uint2*)&vp[0]  = make_uint2(v0.x, v0.y);                         \
            *(uint2*)&vp[2]  = make_uint2(v0.z, v0.w);                         \
            *(uint2*)&vp[4]  = make_uint2(v1.x, v1.y);                         \
            *(uint2*)&vp[6]  = make_uint2(v1.z, v1.w);                         \
            *(uint2*)&vp[8]  = make_uint2(v2.x, v2.y);                         \
            *(uint2*)&vp[10] = make_uint2(v2.z, v2.w);                         \
            *(uint2*)&vp[12] = make_uint2(v3.x, v3.y);                         \
            *(uint2*)&vp[14] = make_uint2(v3.z, v3.w);                         \
        }                                                                      \
        /* E -> mixed W */                                                     \
        float wv[8][4];                                                        \
        _Pragma("unroll")                                                      \
        for (int gg = 0; gg < 8; gg++)                                         \
            { wv[gg][0]=0.f; wv[gg][1]=0.f; wv[gg][2]=0.f; wv[gg][3]=0.f; }    \
        _Pragma("unroll 1")                                                    \
        for (int j = 0; j < 8; j++) {                                          \
            uint2 u = *(const uint2*)&Ebase[(size_t)j*ejstride + (KP0) + kq];  \
            float il = invl[j];                                                \
            float e0 = bf16lo(u.x)*il, e1 = bf16hi(u.x)*il;                    \
            float e2 = bf16lo(u.y)*il, e3 = bf16hi(u.y)*il;                    \
            _Pragma("unroll")                                                  \
            for (int gg = 0; gg < 8; gg++) {                                   \
                float cw = s_ww[gg*8 + j];                                     \
                wv[gg][0] += cw*e0; wv[gg][1] += cw*e1;                        \
                wv[gg][2] += cw*e2; wv[gg][3] += cw*e3;                        \
            }                                                                  \
        }                                                                      \
        _Pragma("unroll")                                                      \
        for (int gg = 0; gg < 8; gg++) {                                       \
            uint32_t* wp = &sWb[(BUF)*AVF_W_BUF + gg*32*WST + er*WST + kq];    \
            *(uint2*)wp = make_uint2(pack_bf16(wv[gg][0], wv[gg][1]),          \
                                     pack_bf16(wv[gg][2], wv[gg][3]));         \
        }                                                                      \
    }

    STAGE_AVF(0, 0);

    float acc[8][2][4];
    #pragma unroll
    for (int h = 0; h < 8; h++)
        #pragma unroll
        for (int dn = 0; dn < 2; dn++)
            #pragma unroll
            for (int e = 0; e < 4; e++) acc[h][dn][e] = 0.f;

    for (int it = 0; it < 64; it++) {
        __syncthreads();
        if (it < 63) {
            const int nb = (it+1) & 1;
            STAGE_AVF(nb, (it+1)*16);
        }
        const int cb = it & 1;
        const uint32_t* Wc = &sWb[cb*AVF_W_BUF];
        const uint32_t* Vc = &sVb[cb*AVF_V_BUF];
        #pragma unroll
        for (int h = 0; h < 8; h++) {
            const uint32_t* Wh = Wc + h*32*WST;
            const uint32_t* Vh = Vc + h*64*WST;
            #pragma unroll
            for (int ck = 0; ck < 2; ck++) {
                uint32_t a0 = Wh[(q0 + g    )*WST + ck*8 + t];
                uint32_t a1 = Wh[(q0 + g + 8)*WST + ck*8 + t];
                uint32_t a2 = Wh[(q0 + g    )*WST + ck*8 + t + 4];
                uint32_t a3 = Wh[(q0 + g + 8)*WST + ck*8 + t + 4];
                #pragma unroll
                for (int dn = 0; dn < 2; dn++) {
                    int d = d0 + dn*8 + g;
                    uint32_t b0 = Vh[d*WST + ck*8 + t];
                    uint32_t b1 = Vh[d*WST + ck*8 + t + 4];
                    mma_bf16(acc[h][dn], a0, a1, a2, a3, b0, b1);
                }
            }
        }
    }
    #undef STAGE_AVF

    // epilogue: + b_w[h]*colsum(V_h) -> g_ao fp32
    #pragma unroll
    for (int h = 0; h < 8; h++) {
        const float bwv = __ldg(&bw[h]);
        const size_t vsb = ((size_t)b*HH + h)*HD;
        #pragma unroll
        for (int dn = 0; dn < 2; dn++) {
            int col = d0 + dn*8 + 2*t;
            float vs0 = g_vs[vsb + col];
            float vs1 = g_vs[vsb + col + 1];
            int r0 = qt + q0 + g, r1 = r0 + 8;
            *(float2*)&g_ao[((size_t)b*SS + r0)*DD + h*64 + col] =
                make_float2(acc[h][0 + 0][0]*0.f + acc[h][dn][0] + bwv*vs0,
                            acc[h][dn][1] + bwv*vs1);
            *(float2*)&g_ao[((size_t)b*SS + r1)*DD + h*64 + col] =
                make_float2(acc[h][dn][2] + bwv*vs0, acc[h][dn][3] + bwv*vs1);
        }
    }
}

// ============================================================================
// Kernel 5: output projection (tf32 mma, fp32 inputs). (R7-proven version.)
// ============================================================================
__global__ __launch_bounds__(256) void k_proj(const float* __restrict__ w,
                                              const float* __restrict__ bias,
                                              float* __restrict__ out) {
    __shared__ uint32_t As[64][68];
    __shared__ uint32_t Bs[64][68];
    const int tid = threadIdx.x;
    const int lane = tid & 31, warp = tid >> 5;
    const int g = lane >> 2, t = lane & 3;
    const int q0 = (warp >> 1) * 16, n0c = (warp & 1) * 32;
    const int m0 = blockIdx.y * 64;
    const int n0 = blockIdx.x * 64;

    float c[4][4] = {};
    for (int k0 = 0; k0 < DD; k0 += 64) {
        stage_tile(As, &g_ao[(size_t)m0 * DD + k0], DD, tid);
        stage_tile(Bs, &w[(size_t)n0 * DD + k0], DD, tid);
        __syncthreads();
        #pragma unroll
        for (int kk = 0; kk < 64; kk += 8) {
            uint32_t a0 = As[q0 + g][kk + t];
            uint32_t a1 = As[q0 + g + 8][kk + t];
            uint32_t a2 = As[q0 + g][kk + t + 4];
            uint32_t a3 = As[q0 + g + 8][kk + t + 4];
            #pragma unroll
            for (int j = 0; j < 4; j++) {
                uint32_t b0 = Bs[n0c + 8*j + g][kk + t];
                uint32_t b1 = Bs[n0c + 8*j + g][kk + t + 4];
                mma_tf32(c[j], a0, a1, a2, a3, b0, b1);
            }
        }
        __syncthreads();
    }
    #pragma unroll
    for (int j = 0; j < 4; j++) {
        int col = n0 + n0c + 8*j + 2*t;
        float2 bv = *(const float2*)&bias[col];
        float2 lo = make_float2(c[j][0] + bv.x, c[j][1] + bv.y);
        float2 hi = make_float2(c[j][2] + bv.x, c[j][3] + bv.y);
        *(float2*)&out[(size_t)(m0 + q0 + g    ) * DD + col] = lo;
        *(float2*)&out[(size_t)(m0 + q0 + g + 8) * DD + col] = hi;
    }
}

// ============================================================================
extern "C" void kernel_launch(void* const* d_in, const int* in_sizes, int n_in,
                              void* d_out, int out_size) {
    const float* x      = (const float*)d_in[0];
    const float* w_qkv  = (const float*)d_in[1];
    const float* w_proj = (const float*)d_in[2];
    const float* b_proj = (const float*)d_in[3];
    const float* w_l    = (const float*)d_in[4];
    const float* b_l    = (const float*)d_in[5];
    const float* w_w    = (const float*)d_in[6];
    const float* b_w    = (const float*)d_in[7];
    float* out = (float*)d_out;

    cudaFuncSetAttribute(k_avfull, cudaFuncAttributeMaxDynamicSharedMemorySize, AVF_SMEM);

    k_qkv   <<<dim3(QKV_N/64, NTOK/64), 256>>>(x, w_qkv);
    k_zero  <<<(BB*HH*SS + 255)/256, 256>>>();
    k_vsum  <<<BB*HH, 256>>>();
    k_packv <<<dim3(BB*HH, SS/64), 256>>>();
    k_scores<<<dim3(SS/64, SS/32, BB), 256>>>(w_l, b_l);
    k_avfull<<<dim3(SS/32, BB), 256, AVF_SMEM>>>(w_w, b_w);
    k_proj  <<<dim3(DD/64, NTOK/64), 256>>>(w_proj, b_proj, out);
}

// round 14
// speedup vs baseline: 1.4616x; 1.4616x over previous
#include <cuda_runtime.h>
#include <cuda_bf16.h>
#include <cstdint>

// Problem constants
#define BB   4
#define SS   2048
#define DD   512
#define HH   8
#define HD   64
#define NTOK (BB*SS)          // 8192
#define QKV_N (3*DD)          // 1536
#define SCALE 0.125f          // HD^-0.5

// ---------------- scratch (__device__ globals) ------------------------------
static __device__ uint32_t g_qb[BB*HH*SS*(HD/2)];      // 8 MB Q bf16 pairs [bh][s][dp]
static __device__ uint32_t g_kb[BB*HH*SS*(HD/2)];      // 8 MB K bf16 pairs [bh][s][dp]
static __device__ float    g_v [BB*HH*SS*HD];          // 16 MB fp32
static __device__ uint32_t g_vb[BB*HH*HD*(SS/2)];      // 8 MB V bf16 pairs [bh][d][kp]
static __device__ uint32_t g_eb[BB*HH*SS*(SS/2)];      // 256 MB E bf16 [b][j][q][kp]
static __device__ uint32_t g_wb[BB*HH*SS*(SS/2)];      // 256 MB W bf16 [b][g][q][kp]
static __device__ float    g_ao[NTOK*DD];              // 16 MB fp32
static __device__ float    g_l[BB*HH*SS];              // softmax denominators
static __device__ float    g_vs[BB*HH*HD];             // colsum of V per (b,h)

// ---------------- helpers ---------------------------------------------------
__device__ __forceinline__ uint32_t f2tf32(float f) {
    uint32_t u;
    asm("cvt.rna.tf32.f32 %0, %1;" : "=r"(u) : "f"(f));
    return u;
}

__device__ __forceinline__ void mma_tf32(float* c,
                                         uint32_t a0, uint32_t a1, uint32_t a2, uint32_t a3,
                                         uint32_t b0, uint32_t b1) {
    asm volatile(
        "mma.sync.aligned.m16n8k8.row.col.f32.tf32.tf32.f32 "
        "{%0,%1,%2,%3}, {%4,%5,%6,%7}, {%8,%9}, {%0,%1,%2,%3};\n"
        : "+f"(c[0]), "+f"(c[1]), "+f"(c[2]), "+f"(c[3])
        : "r"(a0), "r"(a1), "r"(a2), "r"(a3), "r"(b0), "r"(b1));
}

__device__ __forceinline__ void mma_bf16(float* c,
                                         uint32_t a0, uint32_t a1, uint32_t a2, uint32_t a3,
                                         uint32_t b0, uint32_t b1) {
    asm volatile(
        "mma.sync.aligned.m16n8k16.row.col.f32.bf16.bf16.f32 "
        "{%0,%1,%2,%3}, {%4,%5,%6,%7}, {%8,%9}, {%0,%1,%2,%3};\n"
        : "+f"(c[0]), "+f"(c[1]), "+f"(c[2]), "+f"(c[3])
        : "r"(a0), "r"(a1), "r"(a2), "r"(a3), "r"(b0), "r"(b1));
}

__device__ __forceinline__ uint32_t pack_bf16(float lo, float hi) {
    __nv_bfloat162 p = __floats2bfloat162_rn(lo, hi);
    return *reinterpret_cast<uint32_t*>(&p);
}

__device__ __forceinline__ float bf16lo(uint32_t u) { return __uint_as_float(u << 16); }
__device__ __forceinline__ float bf16hi(uint32_t u) { return __uint_as_float(u & 0xffff0000u); }

// Stage a 64x64 fp32 tile (row stride ld floats) into tf32 smem [64][68].
__device__ __forceinline__ void stage_tile(uint32_t (*S)[68], const float* __restrict__ src,
                                           size_t ld, int tid) {
    for (int f = tid; f < 1024; f += 256) {
        int r = f >> 4, c = (f & 15) << 2;
        float4 v = *(const float4*)&src[(size_t)r * ld + c];
        uint4 u;
        u.x = f2tf32(v.x); u.y = f2tf32(v.y); u.z = f2tf32(v.z); u.w = f2tf32(v.w);
        *(uint4*)&S[r][c] = u;
    }
}

#define STRD 36   // smem row stride (u32) for 32-pair bf16 tiles

// ============================================================================
// Kernel 1: QKV GEMM (tf32 mma, fp32 inputs). Q,K -> bf16 pairs; V -> fp32.
// ============================================================================
__global__ __launch_bounds__(256) void k_qkv(const float* __restrict__ x,
                                             const float* __restrict__ w) {
    __shared__ uint32_t As[64][68];
    __shared__ uint32_t Bs[64][68];
    const int tid = threadIdx.x;
    const int lane = tid & 31, warp = tid >> 5;
    const int g = lane >> 2, t = lane & 3;
    const int q0 = (warp >> 1) * 16, n0c = (warp & 1) * 32;
    const int m0 = blockIdx.y * 64;
    const int n0 = blockIdx.x * 64;

    float c[4][4] = {};
    for (int k0 = 0; k0 < DD; k0 += 64) {
        stage_tile(As, &x[(size_t)m0 * DD + k0], DD, tid);
        stage_tile(Bs, &w[(size_t)n0 * DD + k0], DD, tid);
        __syncthreads();
        #pragma unroll
        for (int kk = 0; kk < 64; kk += 8) {
            uint32_t a0 = As[q0 + g][kk + t];
            uint32_t a1 = As[q0 + g + 8][kk + t];
            uint32_t a2 = As[q0 + g][kk + t + 4];
            uint32_t a3 = As[q0 + g + 8][kk + t + 4];
            #pragma unroll
            for (int j = 0; j < 4; j++) {
                uint32_t b0 = Bs[n0c + 8*j + g][kk + t];
                uint32_t b1 = Bs[n0c + 8*j + g][kk + t + 4];
                mma_tf32(c[j], a0, a1, a2, a3, b0, b1);
            }
        }
        __syncthreads();
    }
    const int which = n0 >> 9;
    const int h     = (n0 >> 6) & 7;
    const int b     = m0 / SS;
    const int sbase = m0 % SS;
    const size_t bh = (size_t)b*HH + h;
    if (which == 2) {
        #pragma unroll
        for (int j = 0; j < 4; j++) {
            int col = n0c + 8*j + 2*t;
            *(float2*)&g_v[(bh*SS + sbase + q0 + g    )*HD + col] = make_float2(c[j][0], c[j][1]);
            *(float2*)&g_v[(bh*SS + sbase + q0 + g + 8)*HD + col] = make_float2(c[j][2], c[j][3]);
        }
    } else {
        uint32_t* dst = (which == 0) ? g_qb : g_kb;
        const float mul = (which == 0) ? SCALE : 1.0f;
        #pragma unroll
        for (int j = 0; j < 4; j++) {
            int dp = (n0c + 8*j + 2*t) >> 1;
            dst[(bh*SS + sbase + q0 + g    )*(HD/2) + dp] = pack_bf16(c[j][0]*mul, c[j][1]*mul);
            dst[(bh*SS + sbase + q0 + g + 8)*(HD/2) + dp] = pack_bf16(c[j][2]*mul, c[j][3]*mul);
        }
    }
}

// ============================================================================
// Kernel 2a: zero softmax-denominator accumulator.
// ============================================================================
__global__ __launch_bounds__(256) void k_zero() {
    int i = blockIdx.x * 256 + threadIdx.x;
    if (i < BB*HH*SS) g_l[i] = 0.f;
}

// ============================================================================
// Kernel 2b: V column sums. grid = BB*HH.
// ============================================================================
__global__ __launch_bounds__(256) void k_vsum() {
    __shared__ float red[4][64];
    const int tid = threadIdx.x;
    const int bh = blockIdx.x;
    const int d = tid & 63, seg = tid >> 6;
    const float* vp = &g_v[(size_t)bh * SS * HD];
    float s = 0.f;
    for (int r = seg*512; r < (seg+1)*512; r++) s += vp[(size_t)r*HD + d];
    red[seg][d] = s;
    __syncthreads();
    if (tid < 64)
        g_vs[(size_t)bh*HD + tid] = red[0][tid] + red[1][tid] + red[2][tid] + red[3][tid];
}

// ============================================================================
// Kernel 2c: transpose+pack V -> g_vb[b][h][d][kp] bf16 k-pairs.
// ============================================================================
__global__ __launch_bounds__(256) void k_packv() {
    __shared__ float sT[64][65];
    const int tid = threadIdx.x;
    const int bh = blockIdx.x;
    const int kt = blockIdx.y * 64;
    const float* vp = &g_v[((size_t)bh*SS + kt)*HD];
    for (int i = tid; i < 1024; i += 256) {
        int r = i >> 4, c = (i & 15) << 2;
        float4 v = *(const float4*)&vp[(size_t)r*HD + c];
        sT[r][c] = v.x; sT[r][c+1] = v.y; sT[r][c+2] = v.z; sT[r][c+3] = v.w;
    }
    __syncthreads();
    for (int i = tid; i < 2048; i += 256) {
        int kp = i & 31, d = i >> 5;
        g_vb[((size_t)bh*HD + d)*(SS/2) + (kt >> 1) + kp] =
            pack_bf16(sT[2*kp][d], sT[2*kp+1][d]);
    }
}

// ============================================================================
// Kernel 3: scores + pre-mix (bf16 mma, 32x64 tile, occ 2, double-buffered).
// Stores E = exp(L + b_l) bf16 and accumulates denominators l_j[q].
// ============================================================================
__global__ __launch_bounds__(256, 2) void k_scores(const float* __restrict__ wl,
                                                   const float* __restrict__ bl) {
    __shared__ uint32_t sQ[2][32*STRD];
    __shared__ uint32_t sK[2][64*STRD];
    __shared__ float s_wl[64];
    const int tid = threadIdx.x;
    const int lane = tid & 31, warp = tid >> 5;
    const int g = lane >> 2, t = lane & 3;
    const int q0 = (warp >> 2) * 16;
    const int n0 = (warp & 3) * 16;
    const int kt = blockIdx.x * 64;
    const int qt = blockIdx.y * 32;
    const int b  = blockIdx.z;

    if (tid < 64) s_wl[tid] = wl[tid];

    float blr[8];
    #pragma unroll
    for (int j = 0; j < 8; j++) blr[j] = __ldg(&bl[j]);

    const int qr = tid >> 3, qc = (tid & 7) * 4;
    const int kr = tid >> 2, kc = (tid & 3) * 8;

    float acc[8][8];
    #pragma unroll
    for (int j = 0; j < 8; j++)
        #pragma unroll
        for (int e = 0; e < 8; e++) acc[j][e] = 0.f;

    {
        const uint32_t* Qp = &g_qb[(((size_t)b*HH + 0)*SS + qt)*(HD/2)];
        const uint32_t* Kp = &g_kb[(((size_t)b*HH + 0)*SS + kt)*(HD/2)];
        *(uint4*)&sQ[0][qr*STRD + qc] = *(const uint4*)&Qp[qr*32 + qc];
        *(uint4*)&sK[0][kr*STRD + kc    ] = *(const uint4*)&Kp[kr*32 + kc];
        *(uint4*)&sK[0][kr*STRD + kc + 4] = *(const uint4*)&Kp[kr*32 + kc + 4];
    }

    for (int h = 0; h < 8; h++) {
        __syncthreads();
        if (h < 7) {
            const int nb = (h+1) & 1;
            const uint32_t* Qp = &g_qb[(((size_t)b*HH + h+1)*SS + qt)*(HD/2)];
            const uint32_t* Kp = &g_kb[(((size_t)b*HH + h+1)*SS + kt)*(HD/2)];
            *(uint4*)&sQ[nb][qr*STRD + qc] = *(const uint4*)&Qp[qr*32 + qc];
            *(uint4*)&sK[nb][kr*STRD + kc    ] = *(const uint4*)&Kp[kr*32 + kc];
            *(uint4*)&sK[nb][kr*STRD + kc + 4] = *(const uint4*)&Kp[kr*32 + kc + 4];
        }
        const int cb = h & 1;
        float s[2][4] = {};
        #pragma unroll
        for (int ck = 0; ck < 4; ck++) {
            uint32_t a0 = sQ[cb][(q0 + g    )*STRD + ck*8 + t];
            uint32_t a1 = sQ[cb][(q0 + g + 8)*STRD + ck*8 + t];
            uint32_t a2 = sQ[cb][(q0 + g    )*STRD + ck*8 + t + 4];
            uint32_t a3 = sQ[cb][(q0 + g + 8)*STRD + ck*8 + t + 4];
            #pragma unroll
            for (int jt = 0; jt < 2; jt++) {
                uint32_t b0 = sK[cb][(n0 + jt*8 + g)*STRD + ck*8 + t];
                uint32_t b1 = sK[cb][(n0 + jt*8 + g)*STRD + ck*8 + t + 4];
                mma_bf16(s[jt], a0, a1, a2, a3, b0, b1);
            }
        }
        #pragma unroll
        for (int j = 0; j < 8; j++) {
            float wv = s_wl[j*8 + h];
            #pragma unroll
            for (int jt = 0; jt < 2; jt++)
                #pragma unroll
                for (int e = 0; e < 4; e++)
                    acc[j][jt*4+e] += wv * s[jt][e];
        }
    }

    const int r0 = qt + q0 + g, r1 = r0 + 8;
    #pragma unroll
    for (int j = 0; j < 8; j++) {
        float blv = blr[j];
        size_t rb0 = (((size_t)b*HH + j)*SS + r0) * (SS/2);
        size_t rb1 = (((size_t)b*HH + j)*SS + r1) * (SS/2);
        float l0 = 0.f, l1 = 0.f;
        #pragma unroll
        for (int jt = 0; jt < 2; jt++) {
            int kp = (kt + n0 + jt*8 + 2*t) >> 1;
            float e0 = __expf(acc[j][jt*4+0] + blv);
            float e1 = __expf(acc[j][jt*4+1] + blv);
            float e2 = __expf(acc[j][jt*4+2] + blv);
            float e3 = __expf(acc[j][jt*4+3] + blv);
            g_eb[rb0 + kp] = pack_bf16(e0, e1);
            g_eb[rb1 + kp] = pack_bf16(e2, e3);
            l0 += e0 + e1;
            l1 += e2 + e3;
        }
        l0 += __shfl_xor_sync(0xffffffffu, l0, 1);
        l0 += __shfl_xor_sync(0xffffffffu, l0, 2);
        l1 += __shfl_xor_sync(0xffffffffu, l1, 1);
        l1 += __shfl_xor_sync(0xffffffffu, l1, 2);
        if (t == 0) {
            atomicAdd(&g_l[((size_t)b*HH + j)*SS + r0], l0);
            atomicAdd(&g_l[((size_t)b*HH + j)*SS + r1], l1);
        }
    }
}

// ============================================================================
// Kernel 4: post-softmax mix, streaming, uint4-vectorized.
// Block = (b, q); 256 threads, each owns one uint4 (8 values) of the row.
// Accumulation order over j identical to the uint2 version (bitwise same).
// ============================================================================
__global__ __launch_bounds__(256) void k_mix(const float* __restrict__ ww) {
    __shared__ float s_c[8][8];
    __shared__ float s_inv[8];
    const int tid = threadIdx.x;
    const int q = blockIdx.x & (SS-1);
    const int b = blockIdx.x >> 11;

    if (tid < 8) s_inv[tid] = 1.0f / g_l[((size_t)b*HH + tid)*SS + q];
    __syncthreads();
    if (tid < 64) s_c[tid >> 3][tid & 7] = ww[tid] * s_inv[tid & 7];
    __syncthreads();

    const uint4* E4 = (const uint4*)g_eb;
    uint4* W4 = (uint4*)g_wb;
    const size_t rbase4 = ((size_t)b*HH*SS + q) * (SS/8);   // uint4 units
    const size_t jstep = (size_t)SS*(SS/8);

    uint4 e[8];
    #pragma unroll
    for (int j = 0; j < 8; j++)
        e[j] = E4[rbase4 + j*jstep + tid];

    #pragma unroll
    for (int g = 0; g < 8; g++) {
        float w0=0.f, w1=0.f, w2=0.f, w3=0.f, w4=0.f, w5=0.f, w6=0.f, w7=0.f;
        #pragma unroll
        for (int j = 0; j < 8; j++) {
            float cg = s_c[g][j];
            w0 += cg * bf16lo(e[j].x); w1 += cg * bf16hi(e[j].x);
            w2 += cg * bf16lo(e[j].y); w3 += cg * bf16hi(e[j].y);
            w4 += cg * bf16lo(e[j].z); w5 += cg * bf16hi(e[j].z);
            w6 += cg * bf16lo(e[j].w); w7 += cg * bf16hi(e[j].w);
        }
        uint4 o;
        o.x = pack_bf16(w0, w1); o.y = pack_bf16(w2, w3);
        o.z = pack_bf16(w4, w5); o.w = pack_bf16(w6, w7);
        W4[rbase4 + g*jstep + tid] = o;
    }
}

// ============================================================================
// Kernel 5: AV GEMM (bf16 mma, double-buffered). CTA = (h, qt64, b).
// ============================================================================
__global__ __launch_bounds__(256) void k_av(const float* __restrict__ bw) {
    __shared__ uint32_t sW[2][64*STRD];
    __shared__ uint32_t sV[2][64*STRD];
    const int tid = threadIdx.x;
    const int lane = tid & 31, warp = tid >> 5;
    const int g = lane >> 2, t = lane & 3;
    const int q0 = (warp >> 1) * 16, n0c = (warp & 1) * 32;
    const int h  = blockIdx.x;
    const int qt = blockIdx.y * 64;
    const int b  = blockIdx.z;
    const int r0 = q0 + g, r1 = r0 + 8;

    const uint32_t* Wp = &g_wb[(((size_t)b*HH + h)*SS + qt) * (SS/2)];
    const uint32_t* Vp = &g_vb[((size_t)b*HH + h)*HD*(SS/2)];
    const int sr = tid >> 2, sc = (tid & 3) * 8;

    *(uint4*)&sW[0][sr*STRD + sc    ] = *(const uint4*)&Wp[(size_t)sr*(SS/2) + sc];
    *(uint4*)&sW[0][sr*STRD + sc + 4] = *(const uint4*)&Wp[(size_t)sr*(SS/2) + sc + 4];
    *(uint4*)&sV[0][sr*STRD + sc    ] = *(const uint4*)&Vp[(size_t)sr*(SS/2) + sc];
    *(uint4*)&sV[0][sr*STRD + sc + 4] = *(const uint4*)&Vp[(size_t)sr*(SS/2) + sc + 4];

    float c[4][4] = {};
    for (int i = 0; i < 32; i++) {
        __syncthreads();
        if (i < 31) {
            const int nb = (i+1) & 1;
            const int kp0 = (i+1) * 32;
            *(uint4*)&sW[nb][sr*STRD + sc    ] = *(const uint4*)&Wp[(size_t)sr*(SS/2) + kp0 + sc];
            *(uint4*)&sW[nb][sr*STRD + sc + 4] = *(const uint4*)&Wp[(size_t)sr*(SS/2) + kp0 + sc + 4];
            *(uint4*)&sV[nb][sr*STRD + sc    ] = *(const uint4*)&Vp[(size_t)sr*(SS/2) + kp0 + sc];
            *(uint4*)&sV[nb][sr*STRD + sc + 4] = *(const uint4*)&Vp[(size_t)sr*(SS/2) + kp0 + sc + 4];
        }
        const int cb = i & 1;
        #pragma unroll
        for (int ck = 0; ck < 4; ck++) {
            uint32_t a0 = sW[cb][r0*STRD + ck*8 + t];
            uint32_t a1 = sW[cb][r1*STRD + ck*8 + t];
            uint32_t a2 = sW[cb][r0*STRD + ck*8 + t + 4];
            uint32_t a3 = sW[cb][r1*STRD + ck*8 + t + 4];
            #pragma unroll
            for (int dc = 0; dc < 4; dc++) {
                int d = n0c + dc*8 + g;
                uint32_t b0 = sV[cb][d*STRD + ck*8 + t];
                uint32_t b1 = sV[cb][d*STRD + ck*8 + t + 4];
                mma_bf16(c[dc], a0, a1, a2, a3, b0, b1);
            }
        }
    }
    const float bwv = __ldg(&bw[h]);
    #pragma unroll
    for (int dc = 0; dc < 4; dc++) {
        int col = n0c + dc*8 + 2*t;
        float vs0 = g_vs[((size_t)b*HH + h)*HD + col];
        float vs1 = g_vs[((size_t)b*HH + h)*HD + col + 1];
        float2 lo = make_float2(c[dc][0] + bwv*vs0, c[dc][1] + bwv*vs1);
        float2 hi = make_float2(c[dc][2] + bwv*vs0, c[dc][3] + bwv*vs1);
        *(float2*)&g_ao[((size_t)b*SS + qt + r0)*DD + h*64 + col] = lo;
        *(float2*)&g_ao[((size_t)b*SS + qt + r1)*DD + h*64 + col] = hi;
    }
}

// ============================================================================
// Kernel 6: output projection (tf32 mma, fp32 inputs).
// ============================================================================
__global__ __launch_bounds__(256) void k_proj(const float* __restrict__ w,
                                              const float* __restrict__ bias,
                                              float* __restrict__ out) {
    __shared__ uint32_t As[64][68];
    __shared__ uint32_t Bs[64][68];
    const int tid = threadIdx.x;
    const int lane = tid & 31, warp = tid >> 5;
    const int g = lane >> 2, t = lane & 3;
    const int q0 = (warp >> 1) * 16, n0c = (warp & 1) * 32;
    const int m0 = blockIdx.y * 64;
    const int n0 = blockIdx.x * 64;

    float c[4][4] = {};
    for (int k0 = 0; k0 < DD; k0 += 64) {
        stage_tile(As, &g_ao[(size_t)m0 * DD + k0], DD, tid);
        stage_tile(Bs, &w[(size_t)n0 * DD + k0], DD, tid);
        __syncthreads();
        #pragma unroll
        for (int kk = 0; kk < 64; kk += 8) {
            uint32_t a0 = As[q0 + g][kk + t];
            uint32_t a1 = As[q0 + g + 8][kk + t];
            uint32_t a2 = As[q0 + g][kk + t + 4];
            uint32_t a3 = As[q0 + g + 8][kk + t + 4];
            #pragma unroll
            for (int j = 0; j < 4; j++) {
                uint32_t b0 = Bs[n0c + 8*j + g][kk + t];
                uint32_t b1 = Bs[n0c + 8*j + g][kk + t + 4];
                mma_tf32(c[j], a0, a1, a2, a3, b0, b1);
            }
        }
        __syncthreads();
    }
    #pragma unroll
    for (int j = 0; j < 4; j++) {
        int col = n0 + n0c + 8*j + 2*t;
        float2 bv = *(const float2*)&bias[col];
        float2 lo = make_float2(c[j][0] + bv.x, c[j][1] + bv.y);
        float2 hi = make_float2(c[j][2] + bv.x, c[j][3] + bv.y);
        *(float2*)&out[(size_t)(m0 + q0 + g    ) * DD + col] = lo;
        *(float2*)&out[(size_t)(m0 + q0 + g + 8) * DD + col] = hi;
    }
}

// ============================================================================
extern "C" void kernel_launch(void* const* d_in, const int* in_sizes, int n_in,
                              void* d_out, int out_size) {
    const float* x      = (const float*)d_in[0];
    const float* w_qkv  = (const float*)d_in[1];
    const float* w_proj = (const float*)d_in[2];
    const float* b_proj = (const float*)d_in[3];
    const float* w_l    = (const float*)d_in[4];
    const float* b_l    = (const float*)d_in[5];
    const float* w_w    = (const float*)d_in[6];
    const float* b_w    = (const float*)d_in[7];
    float* out = (float*)d_out;

    k_qkv   <<<dim3(QKV_N/64, NTOK/64), 256>>>(x, w_qkv);
    k_zero  <<<(BB*HH*SS + 255)/256, 256>>>();
    k_vsum  <<<BB*HH, 256>>>();
    k_packv <<<dim3(BB*HH, SS/64), 256>>>();
    k_scores<<<dim3(SS/64, SS/32, BB), 256>>>(w_l, b_l);
    k_mix   <<<BB*SS, 256>>>(w_w);
    k_av    <<<dim3(HH, SS/64, BB), 256>>>(b_w);
    k_proj  <<<dim3(DD/64, NTOK/64), 256>>>(w_proj, b_proj, out);
}

// round 16
// speedup vs baseline: 1.5523x; 1.0620x over previous
#include <cuda_runtime.h>
#include <cuda_bf16.h>
#include <cuda_fp16.h>
#include <cstdint>

// Problem constants
#define BB   4
#define SS   2048
#define DD   512
#define HH   8
#define HD   64
#define NTOK (BB*SS)          // 8192
#define QKV_N (3*DD)          // 1536
#define SCALE 0.125f          // HD^-0.5
#define PD   (DD/2)           // 256 fp16 pairs per row

// ---------------- scratch (__device__ globals) ------------------------------
static __device__ uint32_t g_xh [NTOK*PD];             // 8 MB   x fp16 pairs
static __device__ uint32_t g_wqh[QKV_N*PD];            // 1.5 MB w_qkv fp16 pairs
static __device__ uint32_t g_qb[BB*HH*SS*(HD/2)];      // 8 MB Q bf16 pairs [bh][s][dp]
static __device__ uint32_t g_kb[BB*HH*SS*(HD/2)];      // 8 MB K bf16 pairs [bh][s][dp]
static __device__ float    g_v [BB*HH*SS*HD];          // 16 MB fp32
static __device__ uint32_t g_vb[BB*HH*HD*(SS/2)];      // 8 MB V bf16 pairs [bh][d][kp]
static __device__ uint32_t g_eb[BB*HH*SS*(SS/2)];      // 256 MB E bf16 [b][j][q][kp]
static __device__ uint32_t g_wb[BB*HH*SS*(SS/2)];      // 256 MB W bf16 [b][g][q][kp]
static __device__ float    g_ao[NTOK*DD];              // 16 MB fp32
static __device__ float    g_l[BB*HH*SS];              // softmax denominators
static __device__ float    g_vs[BB*HH*HD];             // colsum of V per (b,h)

// ---------------- helpers ---------------------------------------------------
__device__ __forceinline__ uint32_t f2tf32(float f) {
    uint32_t u;
    asm("cvt.rna.tf32.f32 %0, %1;" : "=r"(u) : "f"(f));
    return u;
}

__device__ __forceinline__ void mma_tf32(float* c,
                                         uint32_t a0, uint32_t a1, uint32_t a2, uint32_t a3,
                                         uint32_t b0, uint32_t b1) {
    asm volatile(
        "mma.sync.aligned.m16n8k8.row.col.f32.tf32.tf32.f32 "
        "{%0,%1,%2,%3}, {%4,%5,%6,%7}, {%8,%9}, {%0,%1,%2,%3};\n"
        : "+f"(c[0]), "+f"(c[1]), "+f"(c[2]), "+f"(c[3])
        : "r"(a0), "r"(a1), "r"(a2), "r"(a3), "r"(b0), "r"(b1));
}

__device__ __forceinline__ void mma_bf16(float* c,
                                         uint32_t a0, uint32_t a1, uint32_t a2, uint32_t a3,
                                         uint32_t b0, uint32_t b1) {
    asm volatile(
        "mma.sync.aligned.m16n8k16.row.col.f32.bf16.bf16.f32 "
        "{%0,%1,%2,%3}, {%4,%5,%6,%7}, {%8,%9}, {%0,%1,%2,%3};\n"
        : "+f"(c[0]), "+f"(c[1]), "+f"(c[2]), "+f"(c[3])
        : "r"(a0), "r"(a1), "r"(a2), "r"(a3), "r"(b0), "r"(b1));
}

__device__ __forceinline__ void mma_fp16(float* c,
                                         uint32_t a0, uint32_t a1, uint32_t a2, uint32_t a3,
                                         uint32_t b0, uint32_t b1) {
    asm volatile(
        "mma.sync.aligned.m16n8k16.row.col.f32.f16.f16.f32 "
        "{%0,%1,%2,%3}, {%4,%5,%6,%7}, {%8,%9}, {%0,%1,%2,%3};\n"
        : "+f"(c[0]), "+f"(c[1]), "+f"(c[2]), "+f"(c[3])
        : "r"(a0), "r"(a1), "r"(a2), "r"(a3), "r"(b0), "r"(b1));
}

__device__ __forceinline__ uint32_t pack_bf16(float lo, float hi) {
    __nv_bfloat162 p = __floats2bfloat162_rn(lo, hi);
    return *reinterpret_cast<uint32_t*>(&p);
}

__device__ __forceinline__ uint32_t pack_fp16(float lo, float hi) {
    __half2 p = __floats2half2_rn(lo, hi);
    return *reinterpret_cast<uint32_t*>(&p);
}

__device__ __forceinline__ float bf16lo(uint32_t u) { return __uint_as_float(u << 16); }
__device__ __forceinline__ float bf16hi(uint32_t u) { return __uint_as_float(u & 0xffff0000u); }

// Stage a 64x64 fp32 tile (row stride ld floats) into tf32 smem [64][68].
__device__ __forceinline__ void stage_tile(uint32_t (*S)[68], const float* __restrict__ src,
                                           size_t ld, int tid) {
    for (int f = tid; f < 1024; f += 256) {
        int r = f >> 4, c = (f & 15) << 2;
        float4 v = *(const float4*)&src[(size_t)r * ld + c];
        uint4 u;
        u.x = f2tf32(v.x); u.y = f2tf32(v.y); u.z = f2tf32(v.z); u.w = f2tf32(v.w);
        *(uint4*)&S[r][c] = u;
    }
}

#define STRD 36   // smem row stride (u32) for 32-pair 16-bit tiles

// ============================================================================
// Kernel 0: pack fp32 -> fp16 pairs (x, w_qkv).
// ============================================================================
__global__ __launch_bounds__(256) void k_pack(const float* __restrict__ src,
                                              int which, int npairs) {
    int i = blockIdx.x * 256 + threadIdx.x;
    if (i >= npairs) return;
    uint32_t* dst = (which == 0) ? g_xh : g_wqh;
    float2 v = *(const float2*)&src[2*i];
    dst[i] = pack_fp16(v.x, v.y);
}

// ============================================================================
// Kernel 1: QKV GEMM (fp16 mma, double-buffered, occ 2).
// Q,K -> bf16 pairs; V -> fp32.
// ============================================================================
__global__ __launch_bounds__(256, 2) void k_qkv() {
    __shared__ uint32_t sA[2][64*STRD];
    __shared__ uint32_t sB[2][64*STRD];
    const int tid = threadIdx.x;
    const int lane = tid & 31, warp = tid >> 5;
    const int g = lane >> 2, t = lane & 3;
    const int q0 = (warp >> 1) * 16, n0c = (warp & 1) * 32;
    const int m0 = blockIdx.y * 64;
    const int n0 = blockIdx.x * 64;
    const int sr = tid >> 2, sc = (tid & 3) * 8;
    const int r0 = q0 + g, r1 = r0 + 8;

    const uint32_t* Ap = &g_xh [(size_t)(m0 + sr) * PD];
    const uint32_t* Bp = &g_wqh[(size_t)(n0 + sr) * PD];

    // stage k-tile 0
    *(uint4*)&sA[0][sr*STRD + sc    ] = *(const uint4*)&Ap[sc];
    *(uint4*)&sA[0][sr*STRD + sc + 4] = *(const uint4*)&Ap[sc + 4];
    *(uint4*)&sB[0][sr*STRD + sc    ] = *(const uint4*)&Bp[sc];
    *(uint4*)&sB[0][sr*STRD + sc + 4] = *(const uint4*)&Bp[sc + 4];

    float c[4][4] = {};
    for (int i = 0; i < 8; i++) {                 // 8 k-tiles of 64 (32 pairs)
        __syncthreads();
        if (i < 7) {
            const int nb = (i+1) & 1;
            const int kp0 = (i+1) * 32;
            *(uint4*)&sA[nb][sr*STRD + sc    ] = *(const uint4*)&Ap[kp0 + sc];
            *(uint4*)&sA[nb][sr*STRD + sc + 4] = *(const uint4*)&Ap[kp0 + sc + 4];
            *(uint4*)&sB[nb][sr*STRD + sc    ] = *(const uint4*)&Bp[kp0 + sc];
            *(uint4*)&sB[nb][sr*STRD + sc + 4] = *(const uint4*)&Bp[kp0 + sc + 4];
        }
        const int cb = i & 1;
        #pragma unroll
        for (int ck = 0; ck < 4; ck++) {
            uint32_t a0 = sA[cb][r0*STRD + ck*8 + t];
            uint32_t a1 = sA[cb][r1*STRD + ck*8 + t];
            uint32_t a2 = sA[cb][r0*STRD + ck*8 + t + 4];
            uint32_t a3 = sA[cb][r1*STRD + ck*8 + t + 4];
            #pragma unroll
            for (int jt = 0; jt < 4; jt++) {
                uint32_t b0 = sB[cb][(n0c + jt*8 + g)*STRD + ck*8 + t];
                uint32_t b1 = sB[cb][(n0c + jt*8 + g)*STRD + ck*8 + t + 4];
                mma_fp16(c[jt], a0, a1, a2, a3, b0, b1);
            }
        }
    }
    const int which = n0 >> 9;
    const int h     = (n0 >> 6) & 7;
    const int b     = m0 / SS;
    const int sbase = m0 % SS;
    const size_t bh = (size_t)b*HH + h;
    if (which == 2) {
        #pragma unroll
        for (int j = 0; j < 4; j++) {
            int col = n0c + 8*j + 2*t;
            *(float2*)&g_v[(bh*SS + sbase + r0)*HD + col] = make_float2(c[j][0], c[j][1]);
            *(float2*)&g_v[(bh*SS + sbase + r1)*HD + col] = make_float2(c[j][2], c[j][3]);
        }
    } else {
        uint32_t* dst = (which == 0) ? g_qb : g_kb;
        const float mul = (which == 0) ? SCALE : 1.0f;
        #pragma unroll
        for (int j = 0; j < 4; j++) {
            int dp = (n0c + 8*j + 2*t) >> 1;
            dst[(bh*SS + sbase + r0)*(HD/2) + dp] = pack_bf16(c[j][0]*mul, c[j][1]*mul);
            dst[(bh*SS + sbase + r1)*(HD/2) + dp] = pack_bf16(c[j][2]*mul, c[j][3]*mul);
        }
    }
}

// ============================================================================
// Kernel 2a: zero softmax-denominator accumulator.
// ============================================================================
__global__ __launch_bounds__(256) void k_zero() {
    int i = blockIdx.x * 256 + threadIdx.x;
    if (i < BB*HH*SS) g_l[i] = 0.f;
}

// ============================================================================
// Kernel 2b: V column sums. grid = BB*HH.
// ============================================================================
__global__ __launch_bounds__(256) void k_vsum() {
    __shared__ float red[4][64];
    const int tid = threadIdx.x;
    const int bh = blockIdx.x;
    const int d = tid & 63, seg = tid >> 6;
    const float* vp = &g_v[(size_t)bh * SS * HD];
    float s = 0.f;
    for (int r = seg*512; r < (seg+1)*512; r++) s += vp[(size_t)r*HD + d];
    red[seg][d] = s;
    __syncthreads();
    if (tid < 64)
        g_vs[(size_t)bh*HD + tid] = red[0][tid] + red[1][tid] + red[2][tid] + red[3][tid];
}

// ============================================================================
// Kernel 2c: transpose+pack V -> g_vb[b][h][d][kp] bf16 k-pairs.
// ============================================================================
__global__ __launch_bounds__(256) void k_packv() {
    __shared__ float sT[64][65];
    const int tid = threadIdx.x;
    const int bh = blockIdx.x;
    const int kt = blockIdx.y * 64;
    const float* vp = &g_v[((size_t)bh*SS + kt)*HD];
    for (int i = tid; i < 1024; i += 256) {
        int r = i >> 4, c = (i & 15) << 2;
        float4 v = *(const float4*)&vp[(size_t)r*HD + c];
        sT[r][c] = v.x; sT[r][c+1] = v.y; sT[r][c+2] = v.z; sT[r][c+3] = v.w;
    }
    __syncthreads();
    for (int i = tid; i < 2048; i += 256) {
        int kp = i & 31, d = i >> 5;
        g_vb[((size_t)bh*HD + d)*(SS/2) + (kt >> 1) + kp] =
            pack_bf16(sT[2*kp][d], sT[2*kp+1][d]);
    }
}

// ============================================================================
// Kernel 3: scores + pre-mix (bf16 mma, 32x64 tile, occ 2, double-buffered).
// Stores E = exp(L + b_l) bf16 and accumulates denominators l_j[q].
// ============================================================================
__global__ __launch_bounds__(256, 2) void k_scores(const float* __restrict__ wl,
                                                   const float* __restrict__ bl) {
    __shared__ uint32_t sQ[2][32*STRD];
    __shared__ uint32_t sK[2][64*STRD];
    __shared__ float s_wl[64];
    const int tid = threadIdx.x;
    const int lane = tid & 31, warp = tid >> 5;
    const int g = lane >> 2, t = lane & 3;
    const int q0 = (warp >> 2) * 16;
    const int n0 = (warp & 3) * 16;
    const int kt = blockIdx.x * 64;
    const int qt = blockIdx.y * 32;
    const int b  = blockIdx.z;

    if (tid < 64) s_wl[tid] = wl[tid];

    float blr[8];
    #pragma unroll
    for (int j = 0; j < 8; j++) blr[j] = __ldg(&bl[j]);

    const int qr = tid >> 3, qc = (tid & 7) * 4;
    const int kr = tid >> 2, kc = (tid & 3) * 8;

    float acc[8][8];
    #pragma unroll
    for (int j = 0; j < 8; j++)
        #pragma unroll
        for (int e = 0; e < 8; e++) acc[j][e] = 0.f;

    {
        const uint32_t* Qp = &g_qb[(((size_t)b*HH + 0)*SS + qt)*(HD/2)];
        const uint32_t* Kp = &g_kb[(((size_t)b*HH + 0)*SS + kt)*(HD/2)];
        *(uint4*)&sQ[0][qr*STRD + qc] = *(const uint4*)&Qp[qr*32 + qc];
        *(uint4*)&sK[0][kr*STRD + kc    ] = *(const uint4*)&Kp[kr*32 + kc];
        *(uint4*)&sK[0][kr*STRD + kc + 4] = *(const uint4*)&Kp[kr*32 + kc + 4];
    }

    for (int h = 0; h < 8; h++) {
        __syncthreads();
        if (h < 7) {
            const int nb = (h+1) & 1;
            const uint32_t* Qp = &g_qb[(((size_t)b*HH + h+1)*SS + qt)*(HD/2)];
            const uint32_t* Kp = &g_kb[(((size_t)b*HH + h+1)*SS + kt)*(HD/2)];
            *(uint4*)&sQ[nb][qr*STRD + qc] = *(const uint4*)&Qp[qr*32 + qc];
            *(uint4*)&sK[nb][kr*STRD + kc    ] = *(const uint4*)&Kp[kr*32 + kc];
            *(uint4*)&sK[nb][kr*STRD + kc + 4] = *(const uint4*)&Kp[kr*32 + kc + 4];
        }
        const int cb = h & 1;
        float s[2][4] = {};
        #pragma unroll
        for (int ck = 0; ck < 4; ck++) {
            uint32_t a0 = sQ[cb][(q0 + g    )*STRD + ck*8 + t];
            uint32_t a1 = sQ[cb][(q0 + g + 8)*STRD + ck*8 + t];
            uint32_t a2 = sQ[cb][(q0 + g    )*STRD + ck*8 + t + 4];
            uint32_t a3 = sQ[cb][(q0 + g + 8)*STRD + ck*8 + t + 4];
            #pragma unroll
            for (int jt = 0; jt < 2; jt++) {
                uint32_t b0 = sK[cb][(n0 + jt*8 + g)*STRD + ck*8 + t];
                uint32_t b1 = sK[cb][(n0 + jt*8 + g)*STRD + ck*8 + t + 4];
                mma_bf16(s[jt], a0, a1, a2, a3, b0, b1);
            }
        }
        #pragma unroll
        for (int j = 0; j < 8; j++) {
            float wv = s_wl[j*8 + h];
            #pragma unroll
            for (int jt = 0; jt < 2; jt++)
                #pragma unroll
                for (int e = 0; e < 4; e++)
                    acc[j][jt*4+e] += wv * s[jt][e];
        }
    }

    const int r0 = qt + q0 + g, r1 = r0 + 8;
    #pragma unroll
    for (int j = 0; j < 8; j++) {
        float blv = blr[j];
        size_t rb0 = (((size_t)b*HH + j)*SS + r0) * (SS/2);
        size_t rb1 = (((size_t)b*HH + j)*SS + r1) * (SS/2);
        float l0 = 0.f, l1 = 0.f;
        #pragma unroll
        for (int jt = 0; jt < 2; jt++) {
            int kp = (kt + n0 + jt*8 + 2*t) >> 1;
            float e0 = __expf(acc[j][jt*4+0] + blv);
            float e1 = __expf(acc[j][jt*4+1] + blv);
            float e2 = __expf(acc[j][jt*4+2] + blv);
            float e3 = __expf(acc[j][jt*4+3] + blv);
            g_eb[rb0 + kp] = pack_bf16(e0, e1);
            g_eb[rb1 + kp] = pack_bf16(e2, e3);
            l0 += e0 + e1;
            l1 += e2 + e3;
        }
        l0 += __shfl_xor_sync(0xffffffffu, l0, 1);
        l0 += __shfl_xor_sync(0xffffffffu, l0, 2);
        l1 += __shfl_xor_sync(0xffffffffu, l1, 1);
        l1 += __shfl_xor_sync(0xffffffffu, l1, 2);
        if (t == 0) {
            atomicAdd(&g_l[((size_t)b*HH + j)*SS + r0], l0);
            atomicAdd(&g_l[((size_t)b*HH + j)*SS + r1], l1);
        }
    }
}

// ============================================================================
// Kernel 4: post-softmax mix, streaming, uint4-vectorized.
// ============================================================================
__global__ __launch_bounds__(256) void k_mix(const float* __restrict__ ww) {
    __shared__ float s_c[8][8];
    __shared__ float s_inv[8];
    const int tid = threadIdx.x;
    const int q = blockIdx.x & (SS-1);
    const int b = blockIdx.x >> 11;

    if (tid < 8) s_inv[tid] = 1.0f / g_l[((size_t)b*HH + tid)*SS + q];
    __syncthreads();
    if (tid < 64) s_c[tid >> 3][tid & 7] = ww[tid] * s_inv[tid & 7];
    __syncthreads();

    const uint4* E4 = (const uint4*)g_eb;
    uint4* W4 = (uint4*)g_wb;
    const size_t rbase4 = ((size_t)b*HH*SS + q) * (SS/8);   // uint4 units
    const size_t jstep = (size_t)SS*(SS/8);

    uint4 e[8];
    #pragma unroll
    for (int j = 0; j < 8; j++)
        e[j] = E4[rbase4 + j*jstep + tid];

    #pragma unroll
    for (int g = 0; g < 8; g++) {
        float w0=0.f, w1=0.f, w2=0.f, w3=0.f, w4=0.f, w5=0.f, w6=0.f, w7=0.f;
        #pragma unroll
        for (int j = 0; j < 8; j++) {
            float cg = s_c[g][j];
            w0 += cg * bf16lo(e[j].x); w1 += cg * bf16hi(e[j].x);
            w2 += cg * bf16lo(e[j].y); w3 += cg * bf16hi(e[j].y);
            w4 += cg * bf16lo(e[j].z); w5 += cg * bf16hi(e[j].z);
            w6 += cg * bf16lo(e[j].w); w7 += cg * bf16hi(e[j].w);
        }
        uint4 o;
        o.x = pack_bf16(w0, w1); o.y = pack_bf16(w2, w3);
        o.z = pack_bf16(w4, w5); o.w = pack_bf16(w6, w7);
        W4[rbase4 + g*jstep + tid] = o;
    }
}

// ============================================================================
// Kernel 5: AV GEMM (bf16 mma, double-buffered). CTA = (h, qt64, b).
// ============================================================================
__global__ __launch_bounds__(256) void k_av(const float* __restrict__ bw) {
    __shared__ uint32_t sW[2][64*STRD];
    __shared__ uint32_t sV[2][64*STRD];
    const int tid = threadIdx.x;
    const int lane = tid & 31, warp = tid >> 5;
    const int g = lane >> 2, t = lane & 3;
    const int q0 = (warp >> 1) * 16, n0c = (warp & 1) * 32;
    const int h  = blockIdx.x;
    const int qt = blockIdx.y * 64;
    const int b  = blockIdx.z;
    const int r0 = q0 + g, r1 = r0 + 8;

    const uint32_t* Wp = &g_wb[(((size_t)b*HH + h)*SS + qt) * (SS/2)];
    const uint32_t* Vp = &g_vb[((size_t)b*HH + h)*HD*(SS/2)];
    const int sr = tid >> 2, sc = (tid & 3) * 8;

    *(uint4*)&sW[0][sr*STRD + sc    ] = *(const uint4*)&Wp[(size_t)sr*(SS/2) + sc];
    *(uint4*)&sW[0][sr*STRD + sc + 4] = *(const uint4*)&Wp[(size_t)sr*(SS/2) + sc + 4];
    *(uint4*)&sV[0][sr*STRD + sc    ] = *(const uint4*)&Vp[(size_t)sr*(SS/2) + sc];
    *(uint4*)&sV[0][sr*STRD + sc + 4] = *(const uint4*)&Vp[(size_t)sr*(SS/2) + sc + 4];

    float c[4][4] = {};
    for (int i = 0; i < 32; i++) {
        __syncthreads();
        if (i < 31) {
            const int nb = (i+1) & 1;
            const int kp0 = (i+1) * 32;
            *(uint4*)&sW[nb][sr*STRD + sc    ] = *(const uint4*)&Wp[(size_t)sr*(SS/2) + kp0 + sc];
            *(uint4*)&sW[nb][sr*STRD + sc + 4] = *(const uint4*)&Wp[(size_t)sr*(SS/2) + kp0 + sc + 4];
            *(uint4*)&sV[nb][sr*STRD + sc    ] = *(const uint4*)&Vp[(size_t)sr*(SS/2) + kp0 + sc];
            *(uint4*)&sV[nb][sr*STRD + sc + 4] = *(const uint4*)&Vp[(size_t)sr*(SS/2) + kp0 + sc + 4];
        }
        const int cb = i & 1;
        #pragma unroll
        for (int ck = 0; ck < 4; ck++) {
            uint32_t a0 = sW[cb][r0*STRD + ck*8 + t];
            uint32_t a1 = sW[cb][r1*STRD + ck*8 + t];
            uint32_t a2 = sW[cb][r0*STRD + ck*8 + t + 4];
            uint32_t a3 = sW[cb][r1*STRD + ck*8 + t + 4];
            #pragma unroll
            for (int dc = 0; dc < 4; dc++) {
                int d = n0c + dc*8 + g;
                uint32_t b0 = sV[cb][d*STRD + ck*8 + t];
                uint32_t b1 = sV[cb][d*STRD + ck*8 + t + 4];
                mma_bf16(c[dc], a0, a1, a2, a3, b0, b1);
            }
        }
    }
    const float bwv = __ldg(&bw[h]);
    #pragma unroll
    for (int dc = 0; dc < 4; dc++) {
        int col = n0c + dc*8 + 2*t;
        float vs0 = g_vs[((size_t)b*HH + h)*HD + col];
        float vs1 = g_vs[((size_t)b*HH + h)*HD + col + 1];
        float2 lo = make_float2(c[dc][0] + bwv*vs0, c[dc][1] + bwv*vs1);
        float2 hi = make_float2(c[dc][2] + bwv*vs0, c[dc][3] + bwv*vs1);
        *(float2*)&g_ao[((size_t)b*SS + qt + r0)*DD + h*64 + col] = lo;
        *(float2*)&g_ao[((size_t)b*SS + qt + r1)*DD + h*64 + col] = hi;
    }
}

// ============================================================================
// Kernel 6: output projection (tf32 mma, fp32 inputs).
// ============================================================================
__global__ __launch_bounds__(256) void k_proj(const float* __restrict__ w,
                                              const float* __restrict__ bias,
                                              float* __restrict__ out) {
    __shared__ uint32_t As[64][68];
    __shared__ uint32_t Bs[64][68];
    const int tid = threadIdx.x;
    const int lane = tid & 31, warp = tid >> 5;
    const int g = lane >> 2, t = lane & 3;
    const int q0 = (warp >> 1) * 16, n0c = (warp & 1) * 32;
    const int m0 = blockIdx.y * 64;
    const int n0 = blockIdx.x * 64;

    float c[4][4] = {};
    for (int k0 = 0; k0 < DD; k0 += 64) {
        stage_tile(As, &g_ao[(size_t)m0 * DD + k0], DD, tid);
        stage_tile(Bs, &w[(size_t)n0 * DD + k0], DD, tid);
        __syncthreads();
        #pragma unroll
        for (int kk = 0; kk < 64; kk += 8) {
            uint32_t a0 = As[q0 + g][kk + t];
            uint32_t a1 = As[q0 + g + 8][kk + t];
            uint32_t a2 = As[q0 + g][kk + t + 4];
            uint32_t a3 = As[q0 + g + 8][kk + t + 4];
            #pragma unroll
            for (int j = 0; j < 4; j++) {
                uint32_t b0 = Bs[n0c + 8*j + g][kk + t];
                uint32_t b1 = Bs[n0c + 8*j + g][kk + t + 4];
                mma_tf32(c[j], a0, a1, a2, a3, b0, b1);
            }
        }
        __syncthreads();
    }
    #pragma unroll
    for (int j = 0; j < 4; j++) {
        int col = n0 + n0c + 8*j + 2*t;
        float2 bv = *(const float2*)&bias[col];
        float2 lo = make_float2(c[j][0] + bv.x, c[j][1] + bv.y);
        float2 hi = make_float2(c[j][2] + bv.x, c[j][3] + bv.y);
        *(float2*)&out[(size_t)(m0 + q0 + g    ) * DD + col] = lo;
        *(float2*)&out[(size_t)(m0 + q0 + g + 8) * DD + col] = hi;
    }
}

// ============================================================================
extern "C" void kernel_launch(void* const* d_in, const int* in_sizes, int n_in,
                              void* d_out, int out_size) {
    const float* x      = (const float*)d_in[0];
    const float* w_qkv  = (const float*)d_in[1];
    const float* w_proj = (const float*)d_in[2];
    const float* b_proj = (const float*)d_in[3];
    const float* w_l    = (const float*)d_in[4];
    const float* b_l    = (const float*)d_in[5];
    const float* w_w    = (const float*)d_in[6];
    const float* b_w    = (const float*)d_in[7];
    float* out = (float*)d_out;

    k_pack  <<<(NTOK*PD + 255)/256, 256>>>(x, 0, NTOK*PD);
    k_pack  <<<(QKV_N*PD + 255)/256, 256>>>(w_qkv, 1, QKV_N*PD);
    k_qkv   <<<dim3(QKV_N/64, NTOK/64), 256>>>();
    k_zero  <<<(BB*HH*SS + 255)/256, 256>>>();
    k_vsum  <<<BB*HH, 256>>>();
    k_packv <<<dim3(BB*HH, SS/64), 256>>>();
    k_scores<<<dim3(SS/64, SS/32, BB), 256>>>(w_l, b_l);
    k_mix   <<<BB*SS, 256>>>(w_w);
    k_av    <<<dim3(HH, SS/64, BB), 256>>>(b_w);
    k_proj  <<<dim3(DD/64, NTOK/64), 256>>>(w_proj, b_proj, out);
}